// round 1
// baseline (speedup 1.0000x reference)
#include <cuda_runtime.h>
#include <cstdint>

// ---------------------------------------------------------------------------
// Problem constants
// ---------------------------------------------------------------------------
#define BATCH 2048
#define CL 256
#define IL 64
#define PC 64          // pointwise out channels
#define L0 255         // stage-A / conv1 length
#define CH1 128
#define CH2 256
#define CH3 256
#define L1 255
#define L2 128
#define L3 64
#define F1 1024
#define F1_IN 16640    // 16384 + 256
#define OUTC 2

// ---------------------------------------------------------------------------
// Scratch (static device memory — no allocations allowed)
// ---------------------------------------------------------------------------
__device__ __align__(128) float g_h0[(size_t)BATCH * PC  * L0];   // 133 MB
__device__ __align__(128) float g_h1[(size_t)BATCH * CH1 * L1];   // 267 MB
__device__ __align__(128) float g_h2[(size_t)BATCH * CH2 * L2];   // 268 MB
__device__ __align__(128) float g_z [(size_t)BATCH * F1_IN];      // 136 MB
__device__ __align__(128) float g_f1[(size_t)BATCH * F1];         // 8.4 MB
__device__ __align__(128) float g_w1t[192 * CH1];
__device__ __align__(128) float g_w2t[384 * CH2];
__device__ __align__(128) float g_w3t[768 * CH3];

// ---------------------------------------------------------------------------
// Weight transpose: w[o][ik] -> wt[ik][o]  (coalesced weight loads in convs)
// ---------------------------------------------------------------------------
__global__ void transpose_w_kernel(const float* __restrict__ w,
                                   float* __restrict__ wt, int O, int IK) {
    int idx = blockIdx.x * blockDim.x + threadIdx.x;
    if (idx < O * IK) {
        int o = idx / IK, ik = idx - o * IK;
        wt[ik * O + o] = w[idx];
    }
}

// ---------------------------------------------------------------------------
// Stage A: y[b,p,c] = relu( Wp0·x0 + bp + Wp1·xcol(c+1) ),  c in [0,255)
// One CTA per batch element, 256 threads.
// ---------------------------------------------------------------------------
__global__ void __launch_bounds__(256) stage_a_kernel(
    const float* __restrict__ x, const float* __restrict__ Wp,
    const float* __restrict__ bp)
{
    __shared__ float wp1s[64 * 65];  // padded stride 65 (bank-conflict free)
    __shared__ float xt[64 * 65];
    __shared__ float s0[64];
    __shared__ float x0s[64];

    const int tid = threadIdx.x;
    const int b = blockIdx.x;
    const float* xb = x + (size_t)b * (CL * IL);

    for (int idx = tid; idx < 4096; idx += 256) {
        int p = idx >> 6, i = idx & 63;
        wp1s[p * 65 + i] = Wp[p * 128 + i * 2 + 1];
    }
    if (tid < 64) x0s[tid] = xb[tid];
    __syncthreads();

    if (tid < 64) {
        float acc = 0.f;
        #pragma unroll 8
        for (int i = 0; i < 64; i++) acc += Wp[tid * 128 + i * 2] * x0s[i];
        s0[tid] = acc + bp[tid];
    }
    __syncthreads();

    const int cl = tid & 63;   // column within tile
    const int pg = tid >> 6;   // channel group (0..3)

    for (int t = 0; t < 4; t++) {
        const int cbase = t * 64;
        for (int idx = tid; idx < 4096; idx += 256) {
            int c = idx >> 6, i = idx & 63;
            int gc = cbase + c;
            xt[c * 65 + i] = (gc < L0) ? xb[(gc + 1) * 64 + i] : 0.f;
        }
        __syncthreads();

        const int c = cbase + cl;
        if (c < L0) {
            #pragma unroll
            for (int half = 0; half < 2; half++) {
                const int p0 = pg * 16 + half * 8;
                float acc[8];
                #pragma unroll
                for (int u = 0; u < 8; u++) acc[u] = s0[p0 + u];
                for (int i = 0; i < 64; i++) {
                    float xv = xt[cl * 65 + i];
                    #pragma unroll
                    for (int u = 0; u < 8; u++)
                        acc[u] += wp1s[(p0 + u) * 65 + i] * xv;
                }
                #pragma unroll
                for (int u = 0; u < 8; u++)
                    g_h0[(size_t)b * (PC * L0) + (p0 + u) * L0 + c] =
                        fmaxf(acc[u], 0.f);
            }
        }
        __syncthreads();
    }
}

// ---------------------------------------------------------------------------
// Generic conv1d (k=3, pad=1) + relu. One CTA per batch, full input in SMEM.
// wt is transposed weights [CIN*3][COUT]. Output layout [b][o*LOUT + pos].
// ---------------------------------------------------------------------------
template<int CIN, int COUT, int LIN, int LOUT, int STRIDE>
__global__ void __launch_bounds__(256) conv_relu_kernel(
    const float* __restrict__ in, const float* __restrict__ wt,
    const float* __restrict__ bias, float* __restrict__ out,
    int outBatchStride)
{
    extern __shared__ float in_s[];
    constexpr int LS = LIN + 2;        // zero halo on both ends
    const int tid = threadIdx.x;
    const int b = blockIdx.x;
    const float* inb = in + (size_t)b * CIN * LIN;

    for (int i = tid; i < CIN; i += 256) {
        in_s[i * LS] = 0.f;
        in_s[i * LS + LIN + 1] = 0.f;
    }
    for (int idx = tid; idx < CIN * LIN; idx += 256) {
        int i = idx / LIN, p = idx - i * LIN;
        in_s[i * LS + p + 1] = inb[idx];
    }
    __syncthreads();

    constexpr int GROUPS = 256 / COUT;
    constexpr int PT = 16;
    constexpr int NTILES = (LOUT + PT - 1) / PT;
    const int o = tid % COUT;
    const int g = tid / COUT;
    const float bv = bias[o];
    float* outb = out + (size_t)b * outBatchStride + o * LOUT;

    for (int t = g; t < NTILES; t += GROUPS) {
        float acc[PT];
        #pragma unroll
        for (int p = 0; p < PT; p++) acc[p] = bv;
        const int base = t * PT;

        for (int i = 0; i < CIN; i++) {
            const float* w = wt + i * 3 * COUT + o;
            float w0 = __ldg(w), w1 = __ldg(w + COUT), w2 = __ldg(w + 2 * COUT);
            const float* row = in_s + i * LS;
            if (STRIDE == 1) {
                float xa = row[base], xb = row[base + 1];
                #pragma unroll
                for (int p = 0; p < PT; p++) {
                    float xc = row[base + p + 2];
                    acc[p] += w0 * xa + w1 * xb + w2 * xc;
                    xa = xb; xb = xc;
                }
            } else {
                float xa = row[2 * base];
                #pragma unroll
                for (int p = 0; p < PT; p++) {
                    float xb2 = row[2 * (base + p) + 1];
                    float xc  = row[2 * (base + p) + 2];
                    acc[p] += w0 * xa + w1 * xb2 + w2 * xc;
                    xa = xc;
                }
            }
        }
        #pragma unroll
        for (int p = 0; p < PT; p++) {
            int pos = base + p;
            if (pos < LOUT) outb[pos] = fmaxf(acc[p], 0.f);
        }
    }
}

// ---------------------------------------------------------------------------
// Branch MLP: x0(64) -> 64 -> 128 -> 256, relu each; writes g_z[:,16384:]
// ---------------------------------------------------------------------------
__global__ void __launch_bounds__(256) branch_kernel(
    const float* __restrict__ x,
    const float* __restrict__ Wb1, const float* __restrict__ bb1,
    const float* __restrict__ Wb2, const float* __restrict__ bb2,
    const float* __restrict__ Wb3, const float* __restrict__ bb3)
{
    __shared__ float x0s[64], f1s[64], f2s[128];
    const int tid = threadIdx.x;
    const int b = blockIdx.x;

    if (tid < 64) x0s[tid] = x[(size_t)b * (CL * IL) + tid];
    __syncthreads();
    if (tid < 64) {
        float acc = bb1[tid];
        #pragma unroll 8
        for (int i = 0; i < 64; i++) acc += Wb1[tid * 64 + i] * x0s[i];
        f1s[tid] = fmaxf(acc, 0.f);
    }
    __syncthreads();
    if (tid < 128) {
        float acc = bb2[tid];
        #pragma unroll 8
        for (int i = 0; i < 64; i++) acc += Wb2[tid * 64 + i] * f1s[i];
        f2s[tid] = fmaxf(acc, 0.f);
    }
    __syncthreads();
    {
        float acc = bb3[tid];
        #pragma unroll 8
        for (int i = 0; i < 128; i++) acc += Wb3[tid * 128 + i] * f2s[i];
        g_z[(size_t)b * F1_IN + 16384 + tid] = fmaxf(acc, 0.f);
    }
}

// ---------------------------------------------------------------------------
// fc1: out[2048,1024] = relu( Z[2048,16640] @ Wfc1[1024,16640]^T + b )
// 128x64 tile, BK=16, 8x4 per thread, 256 threads.
// ---------------------------------------------------------------------------
__global__ void __launch_bounds__(256) fc1_kernel(
    const float* __restrict__ W, const float* __restrict__ bias)
{
    __shared__ float As[16][132];
    __shared__ float Bs[16][68];
    const int tid = threadIdx.x;
    const int m0 = blockIdx.y * 128;
    const int n0 = blockIdx.x * 64;
    const int tx = tid & 15, ty = tid >> 4;

    float acc[8][4];
    #pragma unroll
    for (int mm = 0; mm < 8; mm++)
        #pragma unroll
        for (int nn = 0; nn < 4; nn++) acc[mm][nn] = 0.f;

    const float* Zb = g_z + (size_t)m0 * F1_IN;
    const float* Wb = W + (size_t)n0 * F1_IN;

    for (int k0 = 0; k0 < F1_IN; k0 += 16) {
        #pragma unroll
        for (int r = 0; r < 2; r++) {
            int idx = tid + r * 256;
            int row = idx >> 2, kq = (idx & 3) << 2;
            float4 v = *reinterpret_cast<const float4*>(
                Zb + (size_t)row * F1_IN + k0 + kq);
            As[kq + 0][row] = v.x; As[kq + 1][row] = v.y;
            As[kq + 2][row] = v.z; As[kq + 3][row] = v.w;
        }
        {
            int row = tid >> 2, kq = (tid & 3) << 2;
            float4 v = *reinterpret_cast<const float4*>(
                Wb + (size_t)row * F1_IN + k0 + kq);
            Bs[kq + 0][row] = v.x; Bs[kq + 1][row] = v.y;
            Bs[kq + 2][row] = v.z; Bs[kq + 3][row] = v.w;
        }
        __syncthreads();

        #pragma unroll
        for (int k = 0; k < 16; k++) {
            float a[8], bb[4];
            #pragma unroll
            for (int mm = 0; mm < 8; mm++) a[mm] = As[k][ty * 8 + mm];
            #pragma unroll
            for (int nn = 0; nn < 4; nn++) bb[nn] = Bs[k][tx * 4 + nn];
            #pragma unroll
            for (int mm = 0; mm < 8; mm++)
                #pragma unroll
                for (int nn = 0; nn < 4; nn++)
                    acc[mm][nn] += a[mm] * bb[nn];
        }
        __syncthreads();
    }

    #pragma unroll
    for (int mm = 0; mm < 8; mm++) {
        int m = m0 + ty * 8 + mm;
        #pragma unroll
        for (int nn = 0; nn < 4; nn++) {
            int n = n0 + tx * 4 + nn;
            g_f1[(size_t)m * F1 + n] = fmaxf(acc[mm][nn] + bias[n], 0.f);
        }
    }
}

// ---------------------------------------------------------------------------
// fc2: out[b, 0..1] = g_f1[b,:] @ Wfc2[2,1024]^T + b
// ---------------------------------------------------------------------------
__global__ void __launch_bounds__(128) fc2_kernel(
    const float* __restrict__ W, const float* __restrict__ bias,
    float* __restrict__ out)
{
    __shared__ float red0[4], red1[4];
    const int b = blockIdx.x, tid = threadIdx.x;
    const float* hb = g_f1 + (size_t)b * F1;
    float s0 = 0.f, s1 = 0.f;
    for (int k = tid; k < F1; k += 128) {
        float v = hb[k];
        s0 += v * W[k];
        s1 += v * W[F1 + k];
    }
    #pragma unroll
    for (int off = 16; off > 0; off >>= 1) {
        s0 += __shfl_down_sync(0xffffffffu, s0, off);
        s1 += __shfl_down_sync(0xffffffffu, s1, off);
    }
    if ((tid & 31) == 0) { red0[tid >> 5] = s0; red1[tid >> 5] = s1; }
    __syncthreads();
    if (tid == 0) {
        out[b * 2 + 0] = red0[0] + red0[1] + red0[2] + red0[3] + bias[0];
        out[b * 2 + 1] = red1[0] + red1[1] + red1[2] + red1[3] + bias[1];
    }
}

// ---------------------------------------------------------------------------
// Launch
// ---------------------------------------------------------------------------
extern "C" void kernel_launch(void* const* d_in, const int* in_sizes, int n_in,
                              void* d_out, int out_size)
{
    const float* x    = (const float*)d_in[0];
    const float* Wp   = (const float*)d_in[1];
    const float* bp   = (const float*)d_in[2];
    const float* W1   = (const float*)d_in[3];
    const float* b1   = (const float*)d_in[4];
    const float* W2   = (const float*)d_in[5];
    const float* b2   = (const float*)d_in[6];
    const float* W3   = (const float*)d_in[7];
    const float* b3   = (const float*)d_in[8];
    const float* Wb1  = (const float*)d_in[9];
    const float* bb1  = (const float*)d_in[10];
    const float* Wb2  = (const float*)d_in[11];
    const float* bb2  = (const float*)d_in[12];
    const float* Wb3  = (const float*)d_in[13];
    const float* bb3  = (const float*)d_in[14];
    const float* Wfc1 = (const float*)d_in[15];
    const float* bfc1 = (const float*)d_in[16];
    const float* Wfc2 = (const float*)d_in[17];
    const float* bfc2 = (const float*)d_in[18];
    float* out = (float*)d_out;

    // Resolve scratch symbol addresses via direct symbol reference in kernels;
    // pointers below come from cudaGetSymbolAddress (host API, no alloc).
    void *p_h0, *p_h1, *p_h2, *p_z, *p_w1t, *p_w2t, *p_w3t;
    cudaGetSymbolAddress(&p_h0, g_h0);
    cudaGetSymbolAddress(&p_h1, g_h1);
    cudaGetSymbolAddress(&p_h2, g_h2);
    cudaGetSymbolAddress(&p_z,  g_z);
    cudaGetSymbolAddress(&p_w1t, g_w1t);
    cudaGetSymbolAddress(&p_w2t, g_w2t);
    cudaGetSymbolAddress(&p_w3t, g_w3t);

    const int smem1 = (64  * 257 + 32) * 4;   //  65,920 B
    const int smem2 = (128 * 257 + 32) * 4;   // 131,712 B
    const int smem3 = (256 * 130 + 32) * 4;   // 133,248 B
    cudaFuncSetAttribute(conv_relu_kernel<64, 128, 255, 255, 1>,
                         cudaFuncAttributeMaxDynamicSharedMemorySize, smem1);
    cudaFuncSetAttribute(conv_relu_kernel<128, 256, 255, 128, 2>,
                         cudaFuncAttributeMaxDynamicSharedMemorySize, smem2);
    cudaFuncSetAttribute(conv_relu_kernel<256, 256, 128, 64, 2>,
                         cudaFuncAttributeMaxDynamicSharedMemorySize, smem3);

    // Weight transposes (tiny)
    transpose_w_kernel<<<(128 * 192 + 255) / 256, 256>>>(W1, (float*)p_w1t, 128, 192);
    transpose_w_kernel<<<(256 * 384 + 255) / 256, 256>>>(W2, (float*)p_w2t, 256, 384);
    transpose_w_kernel<<<(256 * 768 + 255) / 256, 256>>>(W3, (float*)p_w3t, 256, 768);

    // Stage A + branch
    stage_a_kernel<<<BATCH, 256>>>(x, Wp, bp);
    branch_kernel<<<BATCH, 256>>>(x, Wb1, bb1, Wb2, bb2, Wb3, bb3);

    // Convs
    conv_relu_kernel<64, 128, 255, 255, 1><<<BATCH, 256, smem1>>>(
        (const float*)p_h0, (const float*)p_w1t, b1, (float*)p_h1, CH1 * L1);
    conv_relu_kernel<128, 256, 255, 128, 2><<<BATCH, 256, smem2>>>(
        (const float*)p_h1, (const float*)p_w2t, b2, (float*)p_h2, CH2 * L2);
    // conv3 writes directly into g_z (flatten layout o*64 + pos), batch stride 16640
    conv_relu_kernel<256, 256, 128, 64, 2><<<BATCH, 256, smem3>>>(
        (const float*)p_h2, (const float*)p_w3t, b3, (float*)p_z, F1_IN);

    // FC head
    dim3 g1(F1 / 64, BATCH / 128);
    fc1_kernel<<<g1, 256>>>(Wfc1, bfc1);
    fc2_kernel<<<BATCH, 128>>>(Wfc2, bfc2, out);
}

// round 2
// speedup vs baseline: 1.0035x; 1.0035x over previous
#include <cuda_runtime.h>
#include <cstdint>

// ---------------------------------------------------------------------------
// Problem constants
// ---------------------------------------------------------------------------
#define BATCH 2048
#define CL 256
#define IL 64
#define PC 64          // pointwise out channels
#define L0 255         // stage-A / conv1 length
#define CH1 128
#define CH2 256
#define CH3 256
#define L1 255
#define L2 128
#define L3 64
#define F1 1024
#define F1_IN 16640    // 16384 + 256
#define OUTC 2

// ---------------------------------------------------------------------------
// Scratch (static device memory — no allocations allowed)
// ---------------------------------------------------------------------------
__device__ __align__(128) float g_h0[(size_t)BATCH * PC  * L0];   // 133 MB
__device__ __align__(128) float g_h1[(size_t)BATCH * CH1 * L1];   // 267 MB
__device__ __align__(128) float g_h2[(size_t)BATCH * CH2 * L2];   // 268 MB
__device__ __align__(128) float g_z [(size_t)BATCH * F1_IN];      // 136 MB
__device__ __align__(128) float g_f1[(size_t)BATCH * F1];         // 8.4 MB
__device__ __align__(128) float g_w1t[192 * CH1];
__device__ __align__(128) float g_w2t[384 * CH2];
__device__ __align__(128) float g_w3t[768 * CH3];

// ---------------------------------------------------------------------------
// Weight transpose: w[o][ik] -> wt[ik][o]  (coalesced weight loads in convs)
// ---------------------------------------------------------------------------
__global__ void transpose_w_kernel(const float* __restrict__ w,
                                   float* __restrict__ wt, int O, int IK) {
    int idx = blockIdx.x * blockDim.x + threadIdx.x;
    if (idx < O * IK) {
        int o = idx / IK, ik = idx - o * IK;
        wt[ik * O + o] = w[idx];
    }
}

// ---------------------------------------------------------------------------
// Stage A: y[b,p,c] = relu( Wp0·x0 + bp + Wp1·xcol(c+1) ),  c in [0,255)
// One CTA per batch element, 256 threads.
// ---------------------------------------------------------------------------
__global__ void __launch_bounds__(256) stage_a_kernel(
    const float* __restrict__ x, const float* __restrict__ Wp,
    const float* __restrict__ bp)
{
    __shared__ float wp1s[64 * 65];  // padded stride 65 (bank-conflict free)
    __shared__ float xt[64 * 65];
    __shared__ float s0[64];
    __shared__ float x0s[64];

    const int tid = threadIdx.x;
    const int b = blockIdx.x;
    const float* xb = x + (size_t)b * (CL * IL);

    for (int idx = tid; idx < 4096; idx += 256) {
        int p = idx >> 6, i = idx & 63;
        wp1s[p * 65 + i] = Wp[p * 128 + i * 2 + 1];
    }
    if (tid < 64) x0s[tid] = xb[tid];
    __syncthreads();

    if (tid < 64) {
        float acc = 0.f;
        #pragma unroll 8
        for (int i = 0; i < 64; i++) acc += Wp[tid * 128 + i * 2] * x0s[i];
        s0[tid] = acc + bp[tid];
    }
    __syncthreads();

    const int cl = tid & 63;   // column within tile
    const int pg = tid >> 6;   // channel group (0..3)

    for (int t = 0; t < 4; t++) {
        const int cbase = t * 64;
        for (int idx = tid; idx < 4096; idx += 256) {
            int c = idx >> 6, i = idx & 63;
            int gc = cbase + c;
            xt[c * 65 + i] = (gc < L0) ? xb[(gc + 1) * 64 + i] : 0.f;
        }
        __syncthreads();

        const int c = cbase + cl;
        if (c < L0) {
            #pragma unroll
            for (int half = 0; half < 2; half++) {
                const int p0 = pg * 16 + half * 8;
                float acc[8];
                #pragma unroll
                for (int u = 0; u < 8; u++) acc[u] = s0[p0 + u];
                for (int i = 0; i < 64; i++) {
                    float xv = xt[cl * 65 + i];
                    #pragma unroll
                    for (int u = 0; u < 8; u++)
                        acc[u] += wp1s[(p0 + u) * 65 + i] * xv;
                }
                #pragma unroll
                for (int u = 0; u < 8; u++)
                    g_h0[(size_t)b * (PC * L0) + (p0 + u) * L0 + c] =
                        fmaxf(acc[u], 0.f);
            }
        }
        __syncthreads();
    }
}

// ---------------------------------------------------------------------------
// Generic conv1d (k=3, pad=1) + relu. One CTA per batch, full input in SMEM.
// wt is transposed weights [CIN*3][COUT]. Output layout [b][o*LOUT + pos].
// ---------------------------------------------------------------------------
template<int CIN, int COUT, int LIN, int LOUT, int STRIDE>
__global__ void __launch_bounds__(256) conv_relu_kernel(
    const float* __restrict__ in, const float* __restrict__ wt,
    const float* __restrict__ bias, float* __restrict__ out,
    int outBatchStride)
{
    extern __shared__ float in_s[];
    constexpr int LS = LIN + 2;        // zero halo on both ends
    const int tid = threadIdx.x;
    const int b = blockIdx.x;
    const float* inb = in + (size_t)b * CIN * LIN;

    for (int i = tid; i < CIN; i += 256) {
        in_s[i * LS] = 0.f;
        in_s[i * LS + LIN + 1] = 0.f;
    }
    for (int idx = tid; idx < CIN * LIN; idx += 256) {
        int i = idx / LIN, p = idx - i * LIN;
        in_s[i * LS + p + 1] = inb[idx];
    }
    __syncthreads();

    constexpr int GROUPS = 256 / COUT;
    constexpr int PT = 16;
    constexpr int NTILES = (LOUT + PT - 1) / PT;
    const int o = tid % COUT;
    const int g = tid / COUT;
    const float bv = bias[o];
    float* outb = out + (size_t)b * outBatchStride + o * LOUT;

    for (int t = g; t < NTILES; t += GROUPS) {
        float acc[PT];
        #pragma unroll
        for (int p = 0; p < PT; p++) acc[p] = bv;
        const int base = t * PT;

        for (int i = 0; i < CIN; i++) {
            const float* w = wt + i * 3 * COUT + o;
            float w0 = __ldg(w), w1 = __ldg(w + COUT), w2 = __ldg(w + 2 * COUT);
            const float* row = in_s + i * LS;
            if (STRIDE == 1) {
                float xa = row[base], xb = row[base + 1];
                #pragma unroll
                for (int p = 0; p < PT; p++) {
                    float xc = row[base + p + 2];
                    acc[p] += w0 * xa + w1 * xb + w2 * xc;
                    xa = xb; xb = xc;
                }
            } else {
                float xa = row[2 * base];
                #pragma unroll
                for (int p = 0; p < PT; p++) {
                    float xb2 = row[2 * (base + p) + 1];
                    float xc  = row[2 * (base + p) + 2];
                    acc[p] += w0 * xa + w1 * xb2 + w2 * xc;
                    xa = xc;
                }
            }
        }
        #pragma unroll
        for (int p = 0; p < PT; p++) {
            int pos = base + p;
            if (pos < LOUT) outb[pos] = fmaxf(acc[p], 0.f);
        }
    }
}

// ---------------------------------------------------------------------------
// Branch MLP: x0(64) -> 64 -> 128 -> 256, relu each; writes g_z[:,16384:]
// ---------------------------------------------------------------------------
__global__ void __launch_bounds__(256) branch_kernel(
    const float* __restrict__ x,
    const float* __restrict__ Wb1, const float* __restrict__ bb1,
    const float* __restrict__ Wb2, const float* __restrict__ bb2,
    const float* __restrict__ Wb3, const float* __restrict__ bb3)
{
    __shared__ float x0s[64], f1s[64], f2s[128];
    const int tid = threadIdx.x;
    const int b = blockIdx.x;

    if (tid < 64) x0s[tid] = x[(size_t)b * (CL * IL) + tid];
    __syncthreads();
    if (tid < 64) {
        float acc = bb1[tid];
        #pragma unroll 8
        for (int i = 0; i < 64; i++) acc += Wb1[tid * 64 + i] * x0s[i];
        f1s[tid] = fmaxf(acc, 0.f);
    }
    __syncthreads();
    if (tid < 128) {
        float acc = bb2[tid];
        #pragma unroll 8
        for (int i = 0; i < 64; i++) acc += Wb2[tid * 64 + i] * f1s[i];
        f2s[tid] = fmaxf(acc, 0.f);
    }
    __syncthreads();
    {
        float acc = bb3[tid];
        #pragma unroll 8
        for (int i = 0; i < 128; i++) acc += Wb3[tid * 128 + i] * f2s[i];
        g_z[(size_t)b * F1_IN + 16384 + tid] = fmaxf(acc, 0.f);
    }
}

// ---------------------------------------------------------------------------
// fc1: out[2048,1024] = relu( Z[2048,16640] @ Wfc1[1024,16640]^T + b )
// 128x64 tile, BK=16, 8x4 per thread, 256 threads.
// ---------------------------------------------------------------------------
__global__ void __launch_bounds__(256) fc1_kernel(
    const float* __restrict__ W, const float* __restrict__ bias)
{
    __shared__ float As[16][132];
    __shared__ float Bs[16][68];
    const int tid = threadIdx.x;
    const int m0 = blockIdx.y * 128;
    const int n0 = blockIdx.x * 64;
    const int tx = tid & 15, ty = tid >> 4;

    float acc[8][4];
    #pragma unroll
    for (int mm = 0; mm < 8; mm++)
        #pragma unroll
        for (int nn = 0; nn < 4; nn++) acc[mm][nn] = 0.f;

    const float* Zb = g_z + (size_t)m0 * F1_IN;
    const float* Wb = W + (size_t)n0 * F1_IN;

    for (int k0 = 0; k0 < F1_IN; k0 += 16) {
        #pragma unroll
        for (int r = 0; r < 2; r++) {
            int idx = tid + r * 256;
            int row = idx >> 2, kq = (idx & 3) << 2;
            float4 v = *reinterpret_cast<const float4*>(
                Zb + (size_t)row * F1_IN + k0 + kq);
            As[kq + 0][row] = v.x; As[kq + 1][row] = v.y;
            As[kq + 2][row] = v.z; As[kq + 3][row] = v.w;
        }
        {
            int row = tid >> 2, kq = (tid & 3) << 2;
            float4 v = *reinterpret_cast<const float4*>(
                Wb + (size_t)row * F1_IN + k0 + kq);
            Bs[kq + 0][row] = v.x; Bs[kq + 1][row] = v.y;
            Bs[kq + 2][row] = v.z; Bs[kq + 3][row] = v.w;
        }
        __syncthreads();

        #pragma unroll
        for (int k = 0; k < 16; k++) {
            float a[8], bb[4];
            #pragma unroll
            for (int mm = 0; mm < 8; mm++) a[mm] = As[k][ty * 8 + mm];
            #pragma unroll
            for (int nn = 0; nn < 4; nn++) bb[nn] = Bs[k][tx * 4 + nn];
            #pragma unroll
            for (int mm = 0; mm < 8; mm++)
                #pragma unroll
                for (int nn = 0; nn < 4; nn++)
                    acc[mm][nn] += a[mm] * bb[nn];
        }
        __syncthreads();
    }

    #pragma unroll
    for (int mm = 0; mm < 8; mm++) {
        int m = m0 + ty * 8 + mm;
        #pragma unroll
        for (int nn = 0; nn < 4; nn++) {
            int n = n0 + tx * 4 + nn;
            g_f1[(size_t)m * F1 + n] = fmaxf(acc[mm][nn] + bias[n], 0.f);
        }
    }
}

// ---------------------------------------------------------------------------
// fc2: out[b, 0..1] = g_f1[b,:] @ Wfc2[2,1024]^T + b
// ---------------------------------------------------------------------------
__global__ void __launch_bounds__(128) fc2_kernel(
    const float* __restrict__ W, const float* __restrict__ bias,
    float* __restrict__ out)
{
    __shared__ float red0[4], red1[4];
    const int b = blockIdx.x, tid = threadIdx.x;
    const float* hb = g_f1 + (size_t)b * F1;
    float s0 = 0.f, s1 = 0.f;
    for (int k = tid; k < F1; k += 128) {
        float v = hb[k];
        s0 += v * W[k];
        s1 += v * W[F1 + k];
    }
    #pragma unroll
    for (int off = 16; off > 0; off >>= 1) {
        s0 += __shfl_down_sync(0xffffffffu, s0, off);
        s1 += __shfl_down_sync(0xffffffffu, s1, off);
    }
    if ((tid & 31) == 0) { red0[tid >> 5] = s0; red1[tid >> 5] = s1; }
    __syncthreads();
    if (tid == 0) {
        out[b * 2 + 0] = red0[0] + red0[1] + red0[2] + red0[3] + bias[0];
        out[b * 2 + 1] = red1[0] + red1[1] + red1[2] + red1[3] + bias[1];
    }
}

// ---------------------------------------------------------------------------
// Launch
// ---------------------------------------------------------------------------
extern "C" void kernel_launch(void* const* d_in, const int* in_sizes, int n_in,
                              void* d_out, int out_size)
{
    const float* x    = (const float*)d_in[0];
    const float* Wp   = (const float*)d_in[1];
    const float* bp   = (const float*)d_in[2];
    const float* W1   = (const float*)d_in[3];
    const float* b1   = (const float*)d_in[4];
    const float* W2   = (const float*)d_in[5];
    const float* b2   = (const float*)d_in[6];
    const float* W3   = (const float*)d_in[7];
    const float* b3   = (const float*)d_in[8];
    const float* Wb1  = (const float*)d_in[9];
    const float* bb1  = (const float*)d_in[10];
    const float* Wb2  = (const float*)d_in[11];
    const float* bb2  = (const float*)d_in[12];
    const float* Wb3  = (const float*)d_in[13];
    const float* bb3  = (const float*)d_in[14];
    const float* Wfc1 = (const float*)d_in[15];
    const float* bfc1 = (const float*)d_in[16];
    const float* Wfc2 = (const float*)d_in[17];
    const float* bfc2 = (const float*)d_in[18];
    float* out = (float*)d_out;

    // Resolve scratch symbol addresses via direct symbol reference in kernels;
    // pointers below come from cudaGetSymbolAddress (host API, no alloc).
    void *p_h0, *p_h1, *p_h2, *p_z, *p_w1t, *p_w2t, *p_w3t;
    cudaGetSymbolAddress(&p_h0, g_h0);
    cudaGetSymbolAddress(&p_h1, g_h1);
    cudaGetSymbolAddress(&p_h2, g_h2);
    cudaGetSymbolAddress(&p_z,  g_z);
    cudaGetSymbolAddress(&p_w1t, g_w1t);
    cudaGetSymbolAddress(&p_w2t, g_w2t);
    cudaGetSymbolAddress(&p_w3t, g_w3t);

    const int smem1 = (64  * 257 + 32) * 4;   //  65,920 B
    const int smem2 = (128 * 257 + 32) * 4;   // 131,712 B
    const int smem3 = (256 * 130 + 32) * 4;   // 133,248 B
    cudaFuncSetAttribute(conv_relu_kernel<64, 128, 255, 255, 1>,
                         cudaFuncAttributeMaxDynamicSharedMemorySize, smem1);
    cudaFuncSetAttribute(conv_relu_kernel<128, 256, 255, 128, 2>,
                         cudaFuncAttributeMaxDynamicSharedMemorySize, smem2);
    cudaFuncSetAttribute(conv_relu_kernel<256, 256, 128, 64, 2>,
                         cudaFuncAttributeMaxDynamicSharedMemorySize, smem3);

    // Weight transposes (tiny)
    transpose_w_kernel<<<(128 * 192 + 255) / 256, 256>>>(W1, (float*)p_w1t, 128, 192);
    transpose_w_kernel<<<(256 * 384 + 255) / 256, 256>>>(W2, (float*)p_w2t, 256, 384);
    transpose_w_kernel<<<(256 * 768 + 255) / 256, 256>>>(W3, (float*)p_w3t, 256, 768);

    // Stage A + branch
    stage_a_kernel<<<BATCH, 256>>>(x, Wp, bp);
    branch_kernel<<<BATCH, 256>>>(x, Wb1, bb1, Wb2, bb2, Wb3, bb3);

    // Convs
    conv_relu_kernel<64, 128, 255, 255, 1><<<BATCH, 256, smem1>>>(
        (const float*)p_h0, (const float*)p_w1t, b1, (float*)p_h1, CH1 * L1);
    conv_relu_kernel<128, 256, 255, 128, 2><<<BATCH, 256, smem2>>>(
        (const float*)p_h1, (const float*)p_w2t, b2, (float*)p_h2, CH2 * L2);
    // conv3 writes directly into g_z (flatten layout o*64 + pos), batch stride 16640
    conv_relu_kernel<256, 256, 128, 64, 2><<<BATCH, 256, smem3>>>(
        (const float*)p_h2, (const float*)p_w3t, b3, (float*)p_z, F1_IN);

    // FC head
    dim3 g1(F1 / 64, BATCH / 128);
    fc1_kernel<<<g1, 256>>>(Wfc1, bfc1);
    fc2_kernel<<<BATCH, 128>>>(Wfc2, bfc2, out);
}

// round 4
// speedup vs baseline: 5.0957x; 5.0780x over previous
#include <cuda_runtime.h>
#include <cuda_bf16.h>
#include <cstdint>

typedef __nv_bfloat16 bf16;

// ---------------------------------------------------------------------------
// Static scratch: split bf16 activation planes (channels-last), fp32 f1/s0,
// pre-split weights in im2col k-order (k = j*CIN + i).
// ---------------------------------------------------------------------------
__device__ __align__(1024) bf16 g_h0h[(size_t)2048 * 255 * 64];
__device__ __align__(1024) bf16 g_h0l[(size_t)2048 * 255 * 64];
__device__ __align__(1024) bf16 g_h1h[(size_t)2048 * 255 * 128];
__device__ __align__(1024) bf16 g_h1l[(size_t)2048 * 255 * 128];
__device__ __align__(1024) bf16 g_h2h[(size_t)2048 * 128 * 256];
__device__ __align__(1024) bf16 g_h2l[(size_t)2048 * 128 * 256];
__device__ __align__(1024) bf16 g_zh [(size_t)2048 * 16640];
__device__ __align__(1024) bf16 g_zl [(size_t)2048 * 16640];
__device__ __align__(1024) float g_f1[(size_t)2048 * 1024];
__device__ __align__(1024) float g_s0[2048 * 64];
__device__ __align__(1024) bf16 g_wah[64 * 64],   g_wal[64 * 64];
__device__ __align__(1024) bf16 g_w1h[128 * 192], g_w1l[128 * 192];
__device__ __align__(1024) bf16 g_w2h[256 * 384], g_w2l[256 * 384];
__device__ __align__(1024) bf16 g_w3h[256 * 768], g_w3l[256 * 768];
__device__ __align__(1024) bf16 g_wfh[(size_t)1024 * 16640];
__device__ __align__(1024) bf16 g_wfl[(size_t)1024 * 16640];

// ---------------------------------------------------------------------------
// Helpers (baseline PTX only: mma.sync / ldmatrix / cp.async — no tcgen05)
// ---------------------------------------------------------------------------
__device__ __forceinline__ uint32_t cvta_smem(const void* p) {
    return (uint32_t)__cvta_generic_to_shared(p);
}
__device__ __forceinline__ void cpa16(uint32_t dst, const void* src, int sz) {
    asm volatile("cp.async.cg.shared.global [%0], [%1], 16, %2;"
                 :: "r"(dst), "l"(src), "r"(sz) : "memory");
}
__device__ __forceinline__ void cp_commit() {
    asm volatile("cp.async.commit_group;" ::: "memory");
}
#define LDM4(r, addr)                                                         \
    asm volatile("ldmatrix.sync.aligned.m8n8.x4.shared.b16 "                  \
                 "{%0,%1,%2,%3}, [%4];"                                       \
                 : "=r"((r)[0]), "=r"((r)[1]), "=r"((r)[2]), "=r"((r)[3])     \
                 : "r"(addr))

__device__ __forceinline__ void mma16816(float* d, const uint32_t* a,
                                         uint32_t b0, uint32_t b1) {
    asm volatile(
        "mma.sync.aligned.m16n8k16.row.col.f32.bf16.bf16.f32 "
        "{%0,%1,%2,%3}, {%4,%5,%6,%7}, {%8,%9}, {%0,%1,%2,%3};"
        : "+f"(d[0]), "+f"(d[1]), "+f"(d[2]), "+f"(d[3])
        : "r"(a[0]), "r"(a[1]), "r"(a[2]), "r"(a[3]), "r"(b0), "r"(b1));
}
__device__ __forceinline__ void split2(float v, bf16& h, bf16& l) {
    h = __float2bfloat16(v);
    l = __float2bfloat16(v - __bfloat162float(h));
}
__device__ __forceinline__ uint32_t pack2(bf16 a, bf16 b) {
    return (uint32_t)__bfloat16_as_ushort(a) |
           ((uint32_t)__bfloat16_as_ushort(b) << 16);
}

// ---------------------------------------------------------------------------
// Unified split-bf16 mma.sync GEMM with fused im2col gather.
// D[m,n] = relu(sum_k A(m,k)*B(n,k) + bias); m=(b,p); k=(j,i); r=STRIDE*p+j+ROFF
// CTA tile 128 x NT, BK=64, 8 warps (4M x 2N), warp tile 32 x NT/2.
// SMEM planes XOR-swizzled (16B granules), ldmatrix fragments, cp.async pipe.
// ---------------------------------------------------------------------------
template<int KTOT, int NT, int CIN, int LIN, int LOUT, int STRIDE, int ROFF,
         int OUTMODE, int NS, bool ROWBIAS, bool AF32, bool OUTF32>
__global__ void __launch_bounds__(256, 1)
gemm_kernel(const float* __restrict__ Af32,
            const bf16* __restrict__ Ahi, const bf16* __restrict__ Alo,
            const bf16* __restrict__ Whi, const bf16* __restrict__ Wlo,
            const float* __restrict__ bias,
            float* __restrict__ Of32, bf16* __restrict__ Ohi,
            bf16* __restrict__ Olo)
{
    constexpr int BK = 64;
    constexpr int NITER = KTOT / BK;
    constexpr int NBUF = (NITER > 1) ? 2 : 1;
    constexpr int ASZ = 128 * 128;            // bytes: 128 rows x 128B (one plane)
    constexpr int BSZ = NT * 128;
    constexpr int BUFB = 2 * ASZ + 2 * BSZ;
    constexpr int NH = NT / 2;                // n per warp
    constexpr int NI = NH / 8;                // n8 tiles per warp
    constexpr int NL = NH / 16;               // ldmatrix.x4 calls per plane

    extern __shared__ __align__(1024) char smem_c[];
    const uint32_t smem0 = cvta_smem(smem_c);

    const int tid = threadIdx.x;
    const int lane = tid & 31;
    const int wid = tid >> 5;
    const int warpM = wid >> 1;
    const int warpN = wid & 1;
    const int n0 = blockIdx.x * NT;
    const int m0 = blockIdx.y * 128;

    float acc[2][NI][4];
    #pragma unroll
    for (int mt = 0; mt < 2; ++mt)
        #pragma unroll
        for (int nt = 0; nt < NI; ++nt)
            #pragma unroll
            for (int e = 0; e < 4; ++e) acc[mt][nt][e] = 0.f;

    // ---- loaders -----------------------------------------------------------
    auto load_tiles = [&](int it, int buf) {
        const int k0 = it * BK;
        const uint32_t sb = smem0 + buf * BUFB;
        #pragma unroll
        for (int rep = 0; rep < 4; ++rep) {           // A: 128 rows x 8 x 16B
            int v = tid + rep * 256;
            int row = v >> 3, q = v & 7;
            int m = m0 + row;
            int b = m / LOUT, p = m - b * LOUT;
            int k = k0 + q * 8;
            int j = k / CIN, i = k - j * CIN;
            int r = STRIDE * p + j + ROFF;
            bool ok = (r >= 0) && (r < LIN);
            size_t off = (size_t)b * ((size_t)LIN * CIN) + (size_t)r * CIN + i;
            uint32_t so = row * 128 + ((q * 16) ^ ((row & 7) << 4));
            int sz = ok ? 16 : 0;
            cpa16(sb + so, Ahi + off, sz);
            cpa16(sb + ASZ + so, Alo + off, sz);
        }
        #pragma unroll
        for (int rep = 0; rep < NT / 32; ++rep) {     // B: NT rows x 8 x 16B
            int v = tid + rep * 256;
            int n = v >> 3, q = v & 7;
            size_t off = (size_t)(n0 + n) * KTOT + k0 + q * 8;
            uint32_t so = n * 128 + ((q * 16) ^ ((n & 7) << 4));
            cpa16(sb + 2 * ASZ + so, Whi + off, 16);
            cpa16(sb + 2 * ASZ + BSZ + so, Wlo + off, 16);
        }
    };

    if constexpr (AF32) {
        // stage-A: single K-tile, fp32 -> split bf16 in registers, sync stores
        #pragma unroll
        for (int rep = 0; rep < 8; ++rep) {           // 128 rows x 16 x 8B
            int v = tid + rep * 256;
            int row = v >> 4, q = v & 15;
            int m = m0 + row;
            int b = m / LOUT, p = m - b * LOUT;
            int i = q * 4;
            int r = p + ROFF;
            bool ok = (r >= 0) && (r < LIN);
            float4 val = ok ? *reinterpret_cast<const float4*>(
                                  Af32 + (size_t)b * ((size_t)LIN * CIN) +
                                  (size_t)r * CIN + i)
                            : make_float4(0.f, 0.f, 0.f, 0.f);
            bf16 h0, h1, h2, h3, l0, l1, l2, l3;
            split2(val.x, h0, l0); split2(val.y, h1, l1);
            split2(val.z, h2, l2); split2(val.w, h3, l3);
            uint32_t so = row * 128 + ((q * 8) ^ ((row & 7) << 4));
            *reinterpret_cast<uint2*>(smem_c + so) =
                make_uint2(pack2(h0, h1), pack2(h2, h3));
            *reinterpret_cast<uint2*>(smem_c + ASZ + so) =
                make_uint2(pack2(l0, l1), pack2(l2, l3));
        }
        #pragma unroll
        for (int rep = 0; rep < NT / 32; ++rep) {     // B sync copy
            int v = tid + rep * 256;
            int n = v >> 3, q = v & 7;
            size_t off = (size_t)(n0 + n) * KTOT + q * 8;
            uint32_t so = n * 128 + ((q * 16) ^ ((n & 7) << 4));
            *reinterpret_cast<uint4*>(smem_c + 2 * ASZ + so) =
                *reinterpret_cast<const uint4*>(Whi + off);
            *reinterpret_cast<uint4*>(smem_c + 2 * ASZ + BSZ + so) =
                *reinterpret_cast<const uint4*>(Wlo + off);
        }
        __syncthreads();
    } else {
        load_tiles(0, 0);
        cp_commit();
    }

    // ---- per-lane ldmatrix addressing constants ----------------------------
    const uint32_t aSwz = (uint32_t)(lane & 7) << 4;
    const uint32_t kbBase = (uint32_t)(lane >> 4) << 4;
    uint32_t rowA[2], rowB[NL];
    #pragma unroll
    for (int mt = 0; mt < 2; ++mt)
        rowA[mt] = (uint32_t)(warpM * 32 + mt * 16 + (lane & 15)) * 128;
    #pragma unroll
    for (int c = 0; c < NL; ++c)
        rowB[c] = (uint32_t)(warpN * NH + c * 16 + (lane & 15)) * 128;

    // ---- mainloop -----------------------------------------------------------
    for (int it = 0; it < NITER; ++it) {
        const int buf = it & (NBUF - 1);
        if constexpr (!AF32) {
            if (it + 1 < NITER) {
                load_tiles(it + 1, (it + 1) & 1);
                cp_commit();
                asm volatile("cp.async.wait_group 1;" ::: "memory");
            } else {
                asm volatile("cp.async.wait_group 0;" ::: "memory");
            }
            __syncthreads();
        }

        const uint32_t sAh = smem0 + buf * BUFB;
        const uint32_t sAl = sAh + ASZ;
        const uint32_t sBh = sAl + ASZ;
        const uint32_t sBl = sBh + BSZ;

        #pragma unroll
        for (int ks = 0; ks < 4; ++ks) {
            const uint32_t kb = ((uint32_t)(ks * 32) + kbBase) ^ aSwz;
            uint32_t ah[2][4], al[2][4];
            #pragma unroll
            for (int mt = 0; mt < 2; ++mt) {
                LDM4(ah[mt], sAh + rowA[mt] + kb);
                LDM4(al[mt], sAl + rowA[mt] + kb);
            }
            #pragma unroll
            for (int c = 0; c < NL; ++c) {
                uint32_t bh[4], bl[4];
                LDM4(bh, sBh + rowB[c] + kb);
                LDM4(bl, sBl + rowB[c] + kb);
                #pragma unroll
                for (int mt = 0; mt < 2; ++mt) {
                    mma16816(acc[mt][2 * c + 0], ah[mt], bh[0], bh[2]);
                    mma16816(acc[mt][2 * c + 1], ah[mt], bh[1], bh[3]);
                    mma16816(acc[mt][2 * c + 0], ah[mt], bl[0], bl[2]);
                    mma16816(acc[mt][2 * c + 1], ah[mt], bl[1], bl[3]);
                    mma16816(acc[mt][2 * c + 0], al[mt], bh[0], bh[2]);
                    mma16816(acc[mt][2 * c + 1], al[mt], bh[1], bh[3]);
                }
            }
        }
        if constexpr (!AF32) {
            if (it + 1 < NITER) __syncthreads();   // protect buf before reissue
        }
    }

    // ---- epilogue (register accumulators) ----------------------------------
    const int tr = lane >> 2;
    const int tc = (lane & 3) * 2;
    #pragma unroll
    for (int mt = 0; mt < 2; ++mt) {
        #pragma unroll
        for (int half = 0; half < 2; ++half) {     // d0,d1 then d2,d3 (row+8)
            const int m = m0 + warpM * 32 + mt * 16 + tr + half * 8;
            const int bb = m / LOUT;
            const int pp = m - bb * LOUT;
            #pragma unroll
            for (int nt = 0; nt < NI; ++nt) {
                const int n = n0 + warpN * NH + nt * 8 + tc;
                const float d0 = acc[mt][nt][half * 2 + 0];
                const float d1 = acc[mt][nt][half * 2 + 1];
                float b0, b1;
                if constexpr (ROWBIAS) {
                    b0 = bias[(size_t)bb * 64 + n];
                    b1 = bias[(size_t)bb * 64 + n + 1];
                } else {
                    b0 = bias[n];
                    b1 = bias[n + 1];
                }
                const float v0 = fmaxf(d0 + b0, 0.f);
                const float v1 = fmaxf(d1 + b1, 0.f);
                if constexpr (OUTMODE == 0) {
                    if constexpr (OUTF32) {
                        *reinterpret_cast<float2*>(Of32 + (size_t)m * NS + n) =
                            make_float2(v0, v1);
                    } else {
                        bf16 h0, h1, l0, l1;
                        split2(v0, h0, l0);
                        split2(v1, h1, l1);
                        size_t o = (size_t)m * NS + n;
                        *reinterpret_cast<uint32_t*>(Ohi + o) = pack2(h0, h1);
                        *reinterpret_cast<uint32_t*>(Olo + o) = pack2(l0, l1);
                    }
                } else {
                    // conv3 flatten: z[b][n*64 + p]
                    bf16 h0, h1, l0, l1;
                    split2(v0, h0, l0);
                    split2(v1, h1, l1);
                    size_t o = (size_t)bb * 16640 + (size_t)n * 64 + pp;
                    Ohi[o] = h0;       Olo[o] = l0;
                    Ohi[o + 64] = h1;  Olo[o + 64] = l1;
                }
            }
        }
    }
}

// ---------------------------------------------------------------------------
// Weight prep kernels (fp32 -> split bf16, im2col k-order)
// ---------------------------------------------------------------------------
__global__ void prep_fc_kernel(const float* __restrict__ W, bf16* hi, bf16* lo,
                               int n) {
    int idx = blockIdx.x * 256 + threadIdx.x;
    if (idx < n) {
        bf16 h, l;
        split2(W[idx], h, l);
        hi[idx] = h; lo[idx] = l;
    }
}
template<int CIN>
__global__ void prep_conv_kernel(const float* __restrict__ W, bf16* hi,
                                 bf16* lo, int O) {
    int idx = blockIdx.x * 256 + threadIdx.x;
    if (idx < O * CIN * 3) {
        int o = idx / (CIN * 3), rem = idx - o * CIN * 3;
        int i = rem / 3, j = rem - i * 3;
        bf16 h, l;
        split2(W[idx], h, l);
        int out = o * (CIN * 3) + j * CIN + i;
        hi[out] = h; lo[out] = l;
    }
}
__global__ void prep_stagea_kernel(const float* __restrict__ Wp, bf16* hi,
                                   bf16* lo) {
    int idx = blockIdx.x * 256 + threadIdx.x;   // 4096
    int p = idx >> 6, i = idx & 63;
    bf16 h, l;
    split2(Wp[p * 128 + i * 2 + 1], h, l);
    hi[idx] = h; lo[idx] = l;
}

// s0[b][p] = bp[p] + sum_i Wp[p][i][0] * x[b][0][i]
__global__ void __launch_bounds__(64) s0_kernel(
    const float* __restrict__ x, const float* __restrict__ Wp,
    const float* __restrict__ bp, float* __restrict__ s0)
{
    __shared__ float xs[64];
    int b = blockIdx.x, t = threadIdx.x;
    xs[t] = x[(size_t)b * 16384 + t];
    __syncthreads();
    float acc = bp[t];
    #pragma unroll 16
    for (int i = 0; i < 64; ++i) acc += Wp[t * 128 + i * 2] * xs[i];
    s0[b * 64 + t] = acc;
}

// Branch MLP -> split z[:,16384:]
__global__ void __launch_bounds__(256) branch_kernel(
    const float* __restrict__ x,
    const float* __restrict__ Wb1, const float* __restrict__ bb1,
    const float* __restrict__ Wb2, const float* __restrict__ bb2,
    const float* __restrict__ Wb3, const float* __restrict__ bb3,
    bf16* __restrict__ zh, bf16* __restrict__ zl)
{
    __shared__ float x0s[64], f1s[64], f2s[128];
    const int tid = threadIdx.x, b = blockIdx.x;
    if (tid < 64) x0s[tid] = x[(size_t)b * 16384 + tid];
    __syncthreads();
    if (tid < 64) {
        float acc = bb1[tid];
        #pragma unroll 8
        for (int i = 0; i < 64; i++) acc += Wb1[tid * 64 + i] * x0s[i];
        f1s[tid] = fmaxf(acc, 0.f);
    }
    __syncthreads();
    if (tid < 128) {
        float acc = bb2[tid];
        #pragma unroll 8
        for (int i = 0; i < 64; i++) acc += Wb2[tid * 64 + i] * f1s[i];
        f2s[tid] = fmaxf(acc, 0.f);
    }
    __syncthreads();
    {
        float acc = bb3[tid];
        #pragma unroll 8
        for (int i = 0; i < 128; i++) acc += Wb3[tid * 128 + i] * f2s[i];
        float v = fmaxf(acc, 0.f);
        bf16 h, l;
        split2(v, h, l);
        size_t o = (size_t)b * 16640 + 16384 + tid;
        zh[o] = h; zl[o] = l;
    }
}

// fc2
__global__ void __launch_bounds__(128) fc2_kernel(
    const float* __restrict__ f1, const float* __restrict__ W,
    const float* __restrict__ bias, float* __restrict__ out)
{
    __shared__ float red0[4], red1[4];
    const int b = blockIdx.x, tid = threadIdx.x;
    const float* hb = f1 + (size_t)b * 1024;
    float s0 = 0.f, s1 = 0.f;
    for (int k = tid; k < 1024; k += 128) {
        float v = hb[k];
        s0 += v * W[k];
        s1 += v * W[1024 + k];
    }
    #pragma unroll
    for (int off = 16; off > 0; off >>= 1) {
        s0 += __shfl_down_sync(0xffffffffu, s0, off);
        s1 += __shfl_down_sync(0xffffffffu, s1, off);
    }
    if ((tid & 31) == 0) { red0[tid >> 5] = s0; red1[tid >> 5] = s1; }
    __syncthreads();
    if (tid == 0) {
        out[b * 2 + 0] = red0[0] + red0[1] + red0[2] + red0[3] + bias[0];
        out[b * 2 + 1] = red1[0] + red1[1] + red1[2] + red1[3] + bias[1];
    }
}

// ---------------------------------------------------------------------------
// Launch
// ---------------------------------------------------------------------------
extern "C" void kernel_launch(void* const* d_in, const int* in_sizes, int n_in,
                              void* d_out, int out_size)
{
    const float* x    = (const float*)d_in[0];
    const float* Wp   = (const float*)d_in[1];
    const float* bp   = (const float*)d_in[2];
    const float* W1   = (const float*)d_in[3];
    const float* b1   = (const float*)d_in[4];
    const float* W2   = (const float*)d_in[5];
    const float* b2   = (const float*)d_in[6];
    const float* W3   = (const float*)d_in[7];
    const float* b3   = (const float*)d_in[8];
    const float* Wb1  = (const float*)d_in[9];
    const float* bb1  = (const float*)d_in[10];
    const float* Wb2  = (const float*)d_in[11];
    const float* bb2  = (const float*)d_in[12];
    const float* Wb3  = (const float*)d_in[13];
    const float* bb3  = (const float*)d_in[14];
    const float* Wfc1 = (const float*)d_in[15];
    const float* bfc1 = (const float*)d_in[16];
    const float* Wfc2 = (const float*)d_in[17];
    const float* bfc2 = (const float*)d_in[18];
    float* out = (float*)d_out;

    static void *h0h, *h0l, *h1h, *h1l, *h2h, *h2l, *zh, *zl, *f1, *s0;
    static void *wah, *wal, *w1h, *w1l, *w2h, *w2l, *w3h, *w3l, *wfh, *wfl;
    static bool init = false;
    if (!init) {
        cudaGetSymbolAddress(&h0h, g_h0h); cudaGetSymbolAddress(&h0l, g_h0l);
        cudaGetSymbolAddress(&h1h, g_h1h); cudaGetSymbolAddress(&h1l, g_h1l);
        cudaGetSymbolAddress(&h2h, g_h2h); cudaGetSymbolAddress(&h2l, g_h2l);
        cudaGetSymbolAddress(&zh,  g_zh);  cudaGetSymbolAddress(&zl,  g_zl);
        cudaGetSymbolAddress(&f1,  g_f1);  cudaGetSymbolAddress(&s0,  g_s0);
        cudaGetSymbolAddress(&wah, g_wah); cudaGetSymbolAddress(&wal, g_wal);
        cudaGetSymbolAddress(&w1h, g_w1h); cudaGetSymbolAddress(&w1l, g_w1l);
        cudaGetSymbolAddress(&w2h, g_w2h); cudaGetSymbolAddress(&w2l, g_w2l);
        cudaGetSymbolAddress(&w3h, g_w3h); cudaGetSymbolAddress(&w3l, g_w3l);
        cudaGetSymbolAddress(&wfh, g_wfh); cudaGetSymbolAddress(&wfl, g_wfl);

        auto setsm = [](const void* f, int bytes) {
            cudaFuncSetAttribute(f, cudaFuncAttributeMaxDynamicSharedMemorySize, bytes);
        };
        setsm((const void*)gemm_kernel<64, 64, 64, 256, 255, 1, 1, 0, 64, true, true, false>, 49152);
        setsm((const void*)gemm_kernel<192, 128, 64, 255, 255, 1, -1, 0, 128, false, false, false>, 131072);
        setsm((const void*)gemm_kernel<384, 128, 128, 255, 128, 2, -1, 0, 256, false, false, false>, 131072);
        setsm((const void*)gemm_kernel<768, 128, 256, 128, 64, 2, -1, 1, 0, false, false, false>, 131072);
        setsm((const void*)gemm_kernel<16640, 128, 16640, 1, 1, 1, 0, 0, 1024, false, false, true>, 131072);
        init = true;
    }

    // weight prep
    prep_stagea_kernel<<<16, 256>>>(Wp, (bf16*)wah, (bf16*)wal);
    prep_conv_kernel<64><<<(128 * 192 + 255) / 256, 256>>>(W1, (bf16*)w1h, (bf16*)w1l, 128);
    prep_conv_kernel<128><<<(256 * 384 + 255) / 256, 256>>>(W2, (bf16*)w2h, (bf16*)w2l, 256);
    prep_conv_kernel<256><<<(256 * 768 + 255) / 256, 256>>>(W3, (bf16*)w3h, (bf16*)w3l, 256);
    prep_fc_kernel<<<(1024 * 16640 + 255) / 256, 256>>>(Wfc1, (bf16*)wfh, (bf16*)wfl, 1024 * 16640);

    // small fp32 side paths
    s0_kernel<<<2048, 64>>>(x, Wp, bp, (float*)s0);
    branch_kernel<<<2048, 256>>>(x, Wb1, bb1, Wb2, bb2, Wb3, bb3,
                                 (bf16*)zh, (bf16*)zl);

    // stage-A: A = x cols 1..255 (fp32->split in-kernel), rowbias = s0
    gemm_kernel<64, 64, 64, 256, 255, 1, 1, 0, 64, true, true, false>
        <<<dim3(1, 4080), 256, 49152>>>(
            x, nullptr, nullptr, (const bf16*)wah, (const bf16*)wal,
            (const float*)s0, nullptr, (bf16*)h0h, (bf16*)h0l);

    // conv1
    gemm_kernel<192, 128, 64, 255, 255, 1, -1, 0, 128, false, false, false>
        <<<dim3(1, 4080), 256, 131072>>>(
            nullptr, (const bf16*)h0h, (const bf16*)h0l,
            (const bf16*)w1h, (const bf16*)w1l, b1,
            nullptr, (bf16*)h1h, (bf16*)h1l);

    // conv2
    gemm_kernel<384, 128, 128, 255, 128, 2, -1, 0, 256, false, false, false>
        <<<dim3(2, 2048), 256, 131072>>>(
            nullptr, (const bf16*)h1h, (const bf16*)h1l,
            (const bf16*)w2h, (const bf16*)w2l, b2,
            nullptr, (bf16*)h2h, (bf16*)h2l);

    // conv3 -> z (flatten layout)
    gemm_kernel<768, 128, 256, 128, 64, 2, -1, 1, 0, false, false, false>
        <<<dim3(2, 1024), 256, 131072>>>(
            nullptr, (const bf16*)h2h, (const bf16*)h2l,
            (const bf16*)w3h, (const bf16*)w3l, b3,
            nullptr, (bf16*)zh, (bf16*)zl);

    // fc1 -> f1 (fp32)
    gemm_kernel<16640, 128, 16640, 1, 1, 1, 0, 0, 1024, false, false, true>
        <<<dim3(8, 16), 256, 131072>>>(
            nullptr, (const bf16*)zh, (const bf16*)zl,
            (const bf16*)wfh, (const bf16*)wfl, bfc1,
            (float*)f1, nullptr, nullptr);

    fc2_kernel<<<2048, 128>>>((const float*)f1, Wfc2, bfc2, out);
}